// round 13
// baseline (speedup 1.0000x reference)
#include <cuda_runtime.h>

// Problem constants: B=2048, F=P*N=4096, C=10
#define F        4096
#define C        10

// wprep geometry: 80 blocks = (c, seg)
#define WSEG     8
#define WPREP_T  256
#define WF       (F / WSEG)
#define NWARP    (WPREP_T / 32)

// lse geometry
#define TX       128                   // threads over f
#define TY       4                     // row groups
#define LTHREADS (TX * TY)             // 512
#define RG       4                     // rows per thread
#define ROWS     (TY * RG)             // 16 rows per block -> grid 128
#define FT       512                   // f per tile
#define NT       (F / FT)              // 8 tiles
#define FPT      (FT / TX)             // 4 f per thread per tile
#define REDW     (LTHREADS / 32)       // 16 warps
#define XT_FLOATS (ROWS * FT)          // 8192 floats = 32KB per x buffer
#define XT_BYTES  (XT_FLOATS * 4)
#define ROW_BYTES (FT * 4)             // 2KB per row per tile
#define SMEM_FLOATS (C * F + 2 * XT_FLOATS)
#define SMEM_BYTES  (SMEM_FLOATS * 4)  // 163840 + 65536 = 229376 B

__device__ float g_pt[C * F];          // pt[c*F + f] = exp(weight[c,f])
__device__ float g_ps[C * WSEG];       // segment partial sums

// ---------- packed f32x2 helpers ----------
__device__ __forceinline__ unsigned long long pack2(float lo, float hi) {
    unsigned long long r;
    asm("mov.b64 %0, {%1, %2};" : "=l"(r) : "f"(lo), "f"(hi));
    return r;
}
__device__ __forceinline__ void unpack2(unsigned long long v, float& lo, float& hi) {
    asm("mov.b64 {%0, %1}, %2;" : "=f"(lo), "=f"(hi) : "l"(v));
}
__device__ __forceinline__ unsigned long long fma2(unsigned long long a,
                                                   unsigned long long b,
                                                   unsigned long long c) {
    unsigned long long d;
    asm("fma.rn.f32x2 %0, %1, %2, %3;" : "=l"(d) : "l"(a), "l"(b), "l"(c));
    return d;
}
// ---------- mbarrier / bulk-copy helpers ----------
__device__ __forceinline__ unsigned int smem_u32(const void* p) {
    return (unsigned int)__cvta_generic_to_shared(p);
}
__device__ __forceinline__ void mbar_init(unsigned int a, unsigned int cnt) {
    asm volatile("mbarrier.init.shared.b64 [%0], %1;" :: "r"(a), "r"(cnt) : "memory");
}
__device__ __forceinline__ void mbar_expect_tx(unsigned int a, unsigned int bytes) {
    asm volatile("mbarrier.arrive.expect_tx.shared.b64 _, [%0], %1;"
                 :: "r"(a), "r"(bytes) : "memory");
}
__device__ __forceinline__ void mbar_wait(unsigned int a, unsigned int parity) {
    asm volatile(
        "{\n\t.reg .pred P;\n\t"
        "WL_%=:\n\t"
        "mbarrier.try_wait.parity.shared.b64 P, [%0], %1, 0x989680;\n\t"
        "@P bra.uni WD_%=;\n\t"
        "bra.uni WL_%=;\n\t"
        "WD_%=:\n\t}"
        :: "r"(a), "r"(parity) : "memory");
}
__device__ __forceinline__ void bulk_g2s(unsigned int dst, const void* src,
                                         unsigned int bytes, unsigned int mbar) {
    asm volatile(
        "cp.async.bulk.shared::cta.global.mbarrier::complete_tx::bytes "
        "[%0], [%1], %2, [%3];"
        :: "r"(dst), "l"(src), "r"(bytes), "r"(mbar) : "memory");
}

// Kernel 1: exp(weight) + segment partial sums.
__global__ void wprep_kernel(const float* __restrict__ w) {
    const int c   = blockIdx.x >> 3;
    const int seg = blockIdx.x & 7;
    const int tid = threadIdx.x;
    const int f   = seg * WF + tid * 2;

    const float2 wv = *reinterpret_cast<const float2*>(w + (size_t)c * F + f);
    const float e0 = __expf(wv.x), e1 = __expf(wv.y);
    *reinterpret_cast<float2*>(g_pt + (size_t)c * F + f) = make_float2(e0, e1);

    float sum = e0 + e1;
    __shared__ float sred[NWARP];
    #pragma unroll
    for (int o = 16; o > 0; o >>= 1) sum += __shfl_xor_sync(0xffffffffu, sum, o);
    if ((tid & 31) == 0) sred[tid >> 5] = sum;
    __syncthreads();
    if (tid == 0) {
        float t = 0.f;
        #pragma unroll
        for (int i = 0; i < NWARP; i++) t += sred[i];
        g_ps[c * WSEG + seg] = t;
    }
}

// Kernel 2: pt smem-resident; x streamed via TMA bulk copies (double buffer);
// packed-f32x2 inner product. 512 threads, 16 rows/block, grid 128.
__global__ __launch_bounds__(LTHREADS, 1) void lse_kernel(const float* __restrict__ x,
                                                          float* __restrict__ out) {
    extern __shared__ float s[];
    float* s_pt = s;                     // C*F floats (160KB)
    float* s_x  = s + C * F;             // 2 x 8192 floats (64KB)
    __shared__ __align__(8) unsigned long long mbar_store[2];

    const int tid = threadIdx.x;
    const int tx  = tid & (TX - 1);
    const int ty  = tid >> 7;
    const int bb  = blockIdx.x * ROWS;   // first row of this block

    const unsigned int mb[2] = { smem_u32(&mbar_store[0]), smem_u32(&mbar_store[1]) };
    const unsigned int sx_addr[2] = { smem_u32(s_x), smem_u32(s_x + XT_FLOATS) };

    // Stage pt once: 10240 float4 over 512 threads, coalesced.
    {
        float4* s4 = reinterpret_cast<float4*>(s_pt);
        const float4* g4 = reinterpret_cast<const float4*>(g_pt);
        #pragma unroll
        for (int k = 0; k < (C * F / 4) / LTHREADS; k++)
            s4[tid + k * LTHREADS] = g4[tid + k * LTHREADS];
    }
    if (tid == 0) { mbar_init(mb[0], 1); mbar_init(mb[1], 1); }
    __syncthreads();   // pt visible + mbarriers initialized

    // Issue tile 0.
    if (tid == 0) {
        mbar_expect_tx(mb[0], XT_BYTES);
        #pragma unroll
        for (int r = 0; r < ROWS; r++)
            bulk_g2s(sx_addr[0] + r * ROW_BYTES,
                     x + (size_t)(bb + r) * F, ROW_BYTES, mb[0]);
    }

    unsigned long long acc2[RG][C];
    #pragma unroll
    for (int r = 0; r < RG; r++)
        #pragma unroll
        for (int c = 0; c < C; c++) acc2[r][c] = 0ull;

    for (int t = 0; t < NT; t++) {
        const int buf = t & 1;
        mbar_wait(mb[buf], (t >> 1) & 1);
        __syncthreads();   // everyone done with tile t-1's buffer; tile t visible

        // Issue tile t+1 into the other buffer (TMA runs behind compute).
        if (tid == 0 && t + 1 < NT) {
            const int nb = (t + 1) & 1;
            mbar_expect_tx(mb[nb], XT_BYTES);
            #pragma unroll
            for (int r = 0; r < ROWS; r++)
                bulk_g2s(sx_addr[nb] + r * ROW_BYTES,
                         x + (size_t)(bb + r) * F + (t + 1) * FT, ROW_BYTES, mb[nb]);
        }

        // Compute tile t: x from smem, exp, packed FFMA2 against pt.
        const float* xs = s_x + buf * XT_FLOATS + (ty * RG) * FT + tx * FPT;
        unsigned long long ea[RG], eb[RG];
        #pragma unroll
        for (int r = 0; r < RG; r++) {
            const float4 xv = *reinterpret_cast<const float4*>(xs + r * FT);
            ea[r] = pack2(__expf(xv.x), __expf(xv.y));
            eb[r] = pack2(__expf(xv.z), __expf(xv.w));
        }
        const float* pbase = s_pt + t * FT + tx * FPT;
        #pragma unroll
        for (int c = 0; c < C; c++) {
            const ulonglong2 pv = *reinterpret_cast<const ulonglong2*>(pbase + c * F);
            #pragma unroll
            for (int r = 0; r < RG; r++) {
                acc2[r][c] = fma2(ea[r], pv.x, acc2[r][c]);
                acc2[r][c] = fma2(eb[r], pv.y, acc2[r][c]);
            }
        }
    }

    // Reduction: reuse x buffer area as scratch.
    __syncthreads();
    float* s_red = s_x;                  // REDW x (RG*C) floats

    #pragma unroll
    for (int r = 0; r < RG; r++)
        #pragma unroll
        for (int c = 0; c < C; c++) {
            float lo, hi;
            unpack2(acc2[r][c], lo, hi);
            float v = lo + hi;
            #pragma unroll
            for (int o = 16; o > 0; o >>= 1) v += __shfl_xor_sync(0xffffffffu, v, o);
            if ((tid & 31) == 0) s_red[(tid >> 5) * (RG * C) + r * C + c] = v;
        }
    __syncthreads();

    if (tid < ROWS * C) {                // 160 threads
        const int row = tid / C, c = tid % C;
        const int tyo = row / RG, r = row % RG;
        float sm = 0.f;
        #pragma unroll
        for (int wi = 0; wi < TX / 32; wi++)
            sm += s_red[(tyo * (TX / 32) + wi) * (RG * C) + r * C + c];
        float z = 0.f;
        #pragma unroll
        for (int k = 0; k < WSEG; k++) z += g_ps[c * WSEG + k];
        out[(size_t)(bb + row) * C + c] = logf(sm) - logf(z);
    }
}

extern "C" void kernel_launch(void* const* d_in, const int* in_sizes, int n_in,
                              void* d_out, int out_size) {
    const float* x = (const float*)d_in[0];   // (2048, 64, 64) fp32
    const float* w = (const float*)d_in[1];   // (10, 4096) fp32
    float* out = (float*)d_out;               // (2048, 10) fp32

    const int B = in_sizes[0] / F;            // 2048

    cudaFuncSetAttribute(lse_kernel, cudaFuncAttributeMaxDynamicSharedMemorySize,
                         SMEM_BYTES);

    wprep_kernel<<<C * WSEG, WPREP_T>>>(w);
    lse_kernel<<<B / ROWS, LTHREADS, SMEM_BYTES>>>(x, out);
}